// round 12
// baseline (speedup 1.0000x reference)
#include <cuda_runtime.h>
#include <cuda_bf16.h>
#include <stdint.h>

#define NN   100000
#define EE   1600000
#define CIN  128
#define CHID 64
#define COUT 40

// Scratch (static __device__ arrays — zero-initialized at module load)
__device__ int    g_dtype;             // 0=int32, 1=int64, 2=float32
__device__ int    g_cnt[NN];           // in-degree; RE-ZEROED by k_scan1 each run
__device__ int    g_rowstart[NN + 1];  // CSR row offsets (N+1 entries)
__device__ int    g_fillpos[NN];       // atomic cursors for CSR fill
__device__ int    g_bsum[128];         // block sums for scan
__device__ int2   g_epk[EE];           // CSR entry: {src, __float_as_int(dinv[src])}
__device__ float  g_dinv[NN];
__device__ float4 g_h1 [(size_t)NN * CHID / 4];
__device__ float4 g_hag[(size_t)NN * CHID / 4];
__device__ float4 g_h2 [(size_t)NN * COUT / 4];

#define SCAN_BLK 1024

// ---------------------------------------------------------------------------
// packed f32x2 FMA: d = a * b + d
__device__ __forceinline__ void ffma2(unsigned long long& d,
                                      unsigned long long a,
                                      unsigned long long b) {
    asm volatile("fma.rn.f32x2 %0, %1, %2, %0;" : "+l"(d) : "l"(a), "l"(b));
}
__device__ __forceinline__ unsigned long long pack2(float lo, float hi) {
    unsigned long long r;
    asm("mov.b64 %0, {%1, %2};" : "=l"(r) : "f"(lo), "f"(hi));
    return r;
}

// In-register dtype probe over the first 32 8-byte pairs (warp 0 only).
// int64 ids < 2^31: all odd 32-bit words zero. float32 ids: as-int huge,
// as-float integral in [0,n). int32: as-int in [0,n).
__device__ __forceinline__ int probe_dtype_warp0(const void* p, int n) {
    const uint2* q = (const uint2*)p;
    uint2 pr = q[threadIdx.x & 31];
    unsigned odd = __ballot_sync(0xffffffffu, pr.y != 0u);
    int iv = (int)pr.x;
    unsigned iok = __ballot_sync(0xffffffffu, iv >= 0 && iv < n);
    float f = __int_as_float(iv);
    unsigned fok = __ballot_sync(0xffffffffu,
                                 f >= 0.0f && f < (float)n && f == floorf(f));
    if (odd == 0u) return 1;
    return (__popc(fok) > __popc(iok)) ? 2 : 0;
}

// scalar decode (fallback / tail)
__device__ __forceinline__ int decode_id(const void* p, size_t idx, int dt, int n) {
    int v;
    if (dt == 1)      v = (int)((const long long*)p)[idx];
    else if (dt == 2) v = (int)((const float*)p)[idx];
    else              v = ((const int*)p)[idx];
    return min(max(v, 0), n - 1);
}

// decode 2 consecutive ids starting at even element index via one vector load
__device__ __forceinline__ void decode2(const void* p, size_t idx, int dt, int n,
                                        int& a, int& b) {
    if (dt == 1) {
        longlong2 v = ((const longlong2*)p)[idx >> 1];
        a = (int)v.x; b = (int)v.y;
    } else if (dt == 2) {
        float2 v = ((const float2*)p)[idx >> 1];
        a = (int)v.x; b = (int)v.y;
    } else {
        int2 v = ((const int2*)p)[idx >> 1];
        a = v.x; b = v.y;
    }
    a = min(max(a, 0), n - 1);
    b = min(max(b, 0), n - 1);
}

// ---------------------------------------------------------------------------
// 1) count in-degree; warp-0 self-probe per block; 2 edges per thread.
__global__ void __launch_bounds__(256) k_count(const void* __restrict__ p, int E, int n) {
    __shared__ int s_dt;
    if (threadIdx.x < 32) {
        int dt = probe_dtype_warp0(p, n);
        if (threadIdx.x == 0) {
            s_dt = dt;
            if (blockIdx.x == 0) g_dtype = dt;   // publish for k_fill
        }
    }
    __syncthreads();
    int dt = s_dt;
    int e = (blockIdx.x * blockDim.x + threadIdx.x) * 2;
    if (e >= E) return;
    if (((E & 1) == 0) && (e + 1 < E)) {
        int d0, d1;
        decode2(p, (size_t)E + e, dt, n, d0, d1);
        atomicAdd(&g_cnt[d0], 1);
        atomicAdd(&g_cnt[d1], 1);
    } else {
        atomicAdd(&g_cnt[decode_id(p, (size_t)E + e, dt, n)], 1);
        if (e + 1 < E)
            atomicAdd(&g_cnt[decode_id(p, (size_t)E + e + 1, dt, n)], 1);
    }
}

// 2a) per-block exclusive scan; also computes dinv and RE-ZEROES g_cnt.
__global__ void k_scan1(int n) {
    __shared__ int s[2][SCAN_BLK];
    int t = threadIdx.x;
    int idx = blockIdx.x * SCAN_BLK + t;
    int v = (idx < n) ? g_cnt[idx] : 0;
    if (idx < n) {
        g_cnt[idx] = 0;                               // restore for next replay
        g_dinv[idx] = rsqrtf((float)v + 1.0f);
    }
    s[0][t] = v;
    __syncthreads();
    int cur = 0;
    for (int off = 1; off < SCAN_BLK; off <<= 1) {
        int nxt = cur ^ 1;
        int add = (t >= off) ? s[cur][t - off] : 0;
        s[nxt][t] = s[cur][t] + add;
        __syncthreads();
        cur = nxt;
    }
    if (idx < n) g_rowstart[idx] = s[cur][t] - v;     // exclusive, in-block
    if (t == SCAN_BLK - 1) g_bsum[blockIdx.x] = s[cur][t];
}

// 2b) fused: add block prefix (warp-reduced over <=98 cached bsums),
//     finalize rowstart, init fill cursors, write rowstart[n]=E.
__global__ void __launch_bounds__(256) k_scan23(int n, int E) {
    __shared__ int s_pref;
    int seg = (blockIdx.x * 256) >> 10;
    if (threadIdx.x < 32) {
        int partial = 0;
        for (int i = threadIdx.x; i < seg; i += 32) partial += g_bsum[i];
        #pragma unroll
        for (int o = 16; o > 0; o >>= 1)
            partial += __shfl_xor_sync(0xffffffffu, partial, o);
        if (threadIdx.x == 0) s_pref = partial;
    }
    __syncthreads();
    int idx = blockIdx.x * 256 + threadIdx.x;
    if (idx == 0) g_rowstart[n] = E;
    if (idx >= n) return;
    int rs = g_rowstart[idx] + s_pref;
    g_rowstart[idx] = rs;
    g_fillpos[idx]  = rs;
}

// 3) CSR fill: {src, dinv[src]} packed; 2 edges per thread.
__global__ void __launch_bounds__(256) k_fill(const void* __restrict__ p, int E, int n) {
    int dt = g_dtype;
    int e = (blockIdx.x * blockDim.x + threadIdx.x) * 2;
    if (e >= E) return;
    int s0, s1, d0, d1;
    bool two = (e + 1 < E);
    if (((E & 1) == 0) && two) {
        decode2(p, (size_t)e, dt, n, s0, s1);
        decode2(p, (size_t)E + e, dt, n, d0, d1);
    } else {
        s0 = decode_id(p, (size_t)e, dt, n);
        d0 = decode_id(p, (size_t)E + e, dt, n);
        if (two) {
            s1 = decode_id(p, (size_t)e + 1, dt, n);
            d1 = decode_id(p, (size_t)E + e + 1, dt, n);
        }
    }
    int pos0 = atomicAdd(&g_fillpos[d0], 1);
    if (pos0 >= 0 && pos0 < E)
        g_epk[pos0] = make_int2(s0, __float_as_int(g_dinv[s0]));
    if (two) {
        int pos1 = atomicAdd(&g_fillpos[d1], 1);
        if (pos1 >= 0 && pos1 < E)
            g_epk[pos1] = make_int2(s1, __float_as_int(g_dinv[s1]));
    }
}

// ---------------------------------------------------------------------------
// GEMM1: g_h1 = x @ W1. One thread per row, FFMA2 inner, LDS.128 weight loads.
__global__ void __launch_bounds__(256) k_gemm1(const float* __restrict__ x,
                                               const float* __restrict__ W, int M) {
    __shared__ __align__(16) float Ws[CIN * CHID];
    for (int i = threadIdx.x; i < CIN * CHID; i += blockDim.x) Ws[i] = W[i];
    __syncthreads();

    int row = blockIdx.x * blockDim.x + threadIdx.x;
    if (row >= M) return;

    unsigned long long acc[CHID / 2];
    #pragma unroll
    for (int c = 0; c < CHID / 2; c++) acc[c] = 0ull;

    const float4* a4 = (const float4*)(x + (size_t)row * CIN);
    for (int k4 = 0; k4 < CIN / 4; k4++) {
        float4 xv = __ldg(a4 + k4);
        #pragma unroll
        for (int j = 0; j < 4; j++) {
            float xk = (j == 0) ? xv.x : (j == 1) ? xv.y : (j == 2) ? xv.z : xv.w;
            unsigned long long xp = pack2(xk, xk);
            const ulonglong2* w2 = (const ulonglong2*)&Ws[(4 * k4 + j) * CHID];
            #pragma unroll
            for (int c = 0; c < CHID / 4; c++) {
                ulonglong2 wv = w2[c];
                ffma2(acc[2 * c + 0], xp, wv.x);
                ffma2(acc[2 * c + 1], xp, wv.y);
            }
        }
    }
    ulonglong2* o = (ulonglong2*)&g_h1[(size_t)row * (CHID / 4)];
    #pragma unroll
    for (int c = 0; c < CHID / 4; c++)
        o[c] = make_ulonglong2(acc[2 * c], acc[2 * c + 1]);
}

// GEMM2: g_h2 = relu(g_hag) @ W2, FFMA2 inner, LDS.128 weight loads.
__global__ void __launch_bounds__(256) k_gemm2(const float* __restrict__ W, int M) {
    __shared__ __align__(16) float Ws[CHID * COUT];
    for (int i = threadIdx.x; i < CHID * COUT; i += blockDim.x) Ws[i] = W[i];
    __syncthreads();

    int row = blockIdx.x * blockDim.x + threadIdx.x;
    if (row >= M) return;

    unsigned long long acc[COUT / 2];
    #pragma unroll
    for (int c = 0; c < COUT / 2; c++) acc[c] = 0ull;

    const float4* a4 = (const float4*)&g_hag[(size_t)row * (CHID / 4)];
    for (int k4 = 0; k4 < CHID / 4; k4++) {
        float4 xv = a4[k4];
        xv.x = fmaxf(xv.x, 0.0f); xv.y = fmaxf(xv.y, 0.0f);
        xv.z = fmaxf(xv.z, 0.0f); xv.w = fmaxf(xv.w, 0.0f);
        #pragma unroll
        for (int j = 0; j < 4; j++) {
            float xk = (j == 0) ? xv.x : (j == 1) ? xv.y : (j == 2) ? xv.z : xv.w;
            unsigned long long xp = pack2(xk, xk);
            const ulonglong2* w2 = (const ulonglong2*)&Ws[(4 * k4 + j) * COUT];
            #pragma unroll
            for (int c = 0; c < COUT / 4; c++) {
                ulonglong2 wv = w2[c];
                ffma2(acc[2 * c + 0], xp, wv.x);
                ffma2(acc[2 * c + 1], xp, wv.y);
            }
        }
    }
    ulonglong2* o = (ulonglong2*)&g_h2[(size_t)row * (COUT / 4)];
    #pragma unroll
    for (int c = 0; c < COUT / 4; c++)
        o[c] = make_ulonglong2(acc[2 * c], acc[2 * c + 1]);
}

// ---------------------------------------------------------------------------
// Gather layer 1 — one warp per node; 2 halves of 16 chunk-lanes.
__global__ void __launch_bounds__(256) k_gather1(const float* __restrict__ b1, int M) {
    int i = blockIdx.x * 8 + threadIdx.y;
    if (i >= M) return;
    int lane = threadIdx.x;
    int half = lane >> 4;                         // 0/1
    int c    = lane & 15;                         // chunk 0..15

    float di = g_dinv[i];
    int start = g_rowstart[i];
    int num   = g_rowstart[i + 1] - start;

    float4 acc = make_float4(0.f, 0.f, 0.f, 0.f);
    #pragma unroll 2
    for (int j = half; j < num; j += 2) {
        int2 pk = g_epk[start + j];
        float w = __int_as_float(pk.y) * di;
        float4 u = g_h1[(size_t)pk.x * (CHID/4) + c];
        acc.x += u.x * w; acc.y += u.y * w; acc.z += u.z * w; acc.w += u.w * w;
    }
    acc.x += __shfl_xor_sync(0xffffffffu, acc.x, 16);
    acc.y += __shfl_xor_sync(0xffffffffu, acc.y, 16);
    acc.z += __shfl_xor_sync(0xffffffffu, acc.z, 16);
    acc.w += __shfl_xor_sync(0xffffffffu, acc.w, 16);
    if (half == 0) {
        float4 v = g_h1[(size_t)i * (CHID/4) + c];
        float4 b = ((const float4*)b1)[c];
        float s = di * di;
        acc.x += v.x * s + b.x; acc.y += v.y * s + b.y;
        acc.z += v.z * s + b.z; acc.w += v.w * s + b.w;
        g_hag[(size_t)i * (CHID/4) + c] = acc;
    }
}

// Gather layer 2 — one warp per node, 3 edge-groups of 10 chunk-lanes.
__global__ void __launch_bounds__(256) k_gather2(const float* __restrict__ b2,
                                                 float* __restrict__ out, int M) {
    int i = blockIdx.x * 8 + threadIdx.y;
    if (i >= M) return;
    int lane = threadIdx.x;
    int half = lane / 10;                         // 0,1,2 (3 = idle lanes 30,31)
    int c    = lane - half * 10;                  // chunk 0..9

    float di = g_dinv[i];
    int start = g_rowstart[i];
    int num   = g_rowstart[i + 1] - start;

    float4 acc = make_float4(0.f, 0.f, 0.f, 0.f);
    if (half < 3) {
        #pragma unroll 2
        for (int j = half; j < num; j += 3) {
            int2 pk = g_epk[start + j];
            float w = __int_as_float(pk.y) * di;
            float4 u = g_h2[(size_t)pk.x * (COUT/4) + c];
            acc.x += u.x * w; acc.y += u.y * w; acc.z += u.z * w; acc.w += u.w * w;
        }
    }
    int l1 = (lane < 10) ? lane + 10 : lane;
    int l2 = (lane < 10) ? lane + 20 : lane;
    float ax = acc.x, ay = acc.y, az = acc.z, aw = acc.w;
    acc.x = ax + __shfl_sync(0xffffffffu, ax, l1) + __shfl_sync(0xffffffffu, ax, l2);
    acc.y = ay + __shfl_sync(0xffffffffu, ay, l1) + __shfl_sync(0xffffffffu, ay, l2);
    acc.z = az + __shfl_sync(0xffffffffu, az, l1) + __shfl_sync(0xffffffffu, az, l2);
    acc.w = aw + __shfl_sync(0xffffffffu, aw, l1) + __shfl_sync(0xffffffffu, aw, l2);
    if (lane < 10) {
        float4 v = g_h2[(size_t)i * (COUT/4) + c];
        float4 b = ((const float4*)b2)[c];
        float s = di * di;
        acc.x += v.x * s + b.x; acc.y += v.y * s + b.y;
        acc.z += v.z * s + b.z; acc.w += v.w * s + b.w;
        ((float4*)out)[(size_t)i * (COUT/4) + c] = acc;
    }
}

// ---------------------------------------------------------------------------
extern "C" void kernel_launch(void* const* d_in, const int* in_sizes, int n_in,
                              void* d_out, int out_size) {
    int M = out_size / COUT;                 // 100000

    const float* x  = nullptr;
    const float* W1 = nullptr;
    const float* b1 = nullptr;
    const float* W2 = nullptr;
    const float* b2 = nullptr;
    const void*  ei = nullptr;
    int eiElems = 0;
    for (int i = 0; i < n_in; i++) {
        int s = in_sizes[i];
        if      (s == M * CIN)      x  = (const float*)d_in[i];
        else if (s == CIN * CHID)   W1 = (const float*)d_in[i];
        else if (s == CHID)         b1 = (const float*)d_in[i];
        else if (s == CHID * COUT)  W2 = (const float*)d_in[i];
        else if (s == COUT)         b2 = (const float*)d_in[i];
        else { ei = d_in[i]; eiElems = s; }
    }
    if (!x || !W1 || !b1 || !W2 || !b2 || !ei) return;

    int E = eiElems / 2;
    if (E > EE) E = EE;
    if (M > NN) M = NN;
    int nb   = (M + SCAN_BLK - 1) / SCAN_BLK;     // 98
    int nbE2 = (E / 2 + 255) / 256;               // 3125 (2 edges/thread)
    int nbG  = (M + 255) / 256;                   // 391

    float* out = (float*)d_out;

    k_count <<<nbE2, 256>>>(ei, E, M);            // probe + count
    k_scan1 <<<nb, SCAN_BLK>>>(M);                // scan + dinv + cnt re-zero
    k_scan23<<<nbG, 256>>>(M, E);                 // finalize offsets + cursors
    k_fill  <<<nbE2, 256>>>(ei, E, M);            // CSR fill (packed entries)

    k_gemm1<<<nbG, 256>>>(x, W1, M);
    {
        dim3 bd(32, 8);
        k_gather1<<<(M + 7) / 8, bd>>>(b1, M);
    }
    k_gemm2<<<nbG, 256>>>(W2, M);
    {
        dim3 bd(32, 8);
        k_gather2<<<(M + 7) / 8, bd>>>(b2, out, M);
    }
}

// round 13
// speedup vs baseline: 1.1543x; 1.1543x over previous
#include <cuda_runtime.h>
#include <cuda_bf16.h>
#include <stdint.h>

#define NN   100000
#define EE   1600000
#define CIN  128
#define CHID 64
#define COUT 40

// Scratch (static __device__ arrays — zero-initialized at module load)
__device__ int    g_dtype;             // 0=int32, 1=int64, 2=float32
__device__ int    g_cnt[NN];           // in-degree; RE-ZEROED by k_scan1 each run
__device__ int    g_rowstart[NN + 1];  // CSR row offsets (N+1 entries)
__device__ int    g_fillpos[NN];       // atomic cursors for CSR fill
__device__ int    g_bsum[128];         // block sums for scan
__device__ int    g_eidx[EE];          // CSR entry: src node id (4 B)
__device__ float  g_dinv[NN];
__device__ float4 g_h1 [(size_t)NN * CHID / 4];   // dinv[i] * (x@W1)[i]  (prescaled)
__device__ float4 g_hag[(size_t)NN * CHID / 4];   // layer-1 output (with b1)
__device__ float4 g_h2 [(size_t)NN * COUT / 4];   // dinv[i] * (relu(hag)@W2)[i]

#define SCAN_BLK 1024

// ---------------------------------------------------------------------------
// packed f32x2 ops
__device__ __forceinline__ void ffma2(unsigned long long& d,
                                      unsigned long long a,
                                      unsigned long long b) {
    asm volatile("fma.rn.f32x2 %0, %1, %2, %0;" : "+l"(d) : "l"(a), "l"(b));
}
__device__ __forceinline__ void fmul2(unsigned long long& d, unsigned long long a) {
    asm volatile("mul.rn.f32x2 %0, %0, %1;" : "+l"(d) : "l"(a));
}
__device__ __forceinline__ unsigned long long pack2(float lo, float hi) {
    unsigned long long r;
    asm("mov.b64 %0, {%1, %2};" : "=l"(r) : "f"(lo), "f"(hi));
    return r;
}

// In-register dtype probe over the first 32 8-byte pairs (warp 0 only).
__device__ __forceinline__ int probe_dtype_warp0(const void* p, int n) {
    const uint2* q = (const uint2*)p;
    uint2 pr = q[threadIdx.x & 31];
    unsigned odd = __ballot_sync(0xffffffffu, pr.y != 0u);
    int iv = (int)pr.x;
    unsigned iok = __ballot_sync(0xffffffffu, iv >= 0 && iv < n);
    float f = __int_as_float(iv);
    unsigned fok = __ballot_sync(0xffffffffu,
                                 f >= 0.0f && f < (float)n && f == floorf(f));
    if (odd == 0u) return 1;
    return (__popc(fok) > __popc(iok)) ? 2 : 0;
}

__device__ __forceinline__ int decode_id(const void* p, size_t idx, int dt, int n) {
    int v;
    if (dt == 1)      v = (int)((const long long*)p)[idx];
    else if (dt == 2) v = (int)((const float*)p)[idx];
    else              v = ((const int*)p)[idx];
    return min(max(v, 0), n - 1);
}

__device__ __forceinline__ void decode2(const void* p, size_t idx, int dt, int n,
                                        int& a, int& b) {
    if (dt == 1) {
        longlong2 v = ((const longlong2*)p)[idx >> 1];
        a = (int)v.x; b = (int)v.y;
    } else if (dt == 2) {
        float2 v = ((const float2*)p)[idx >> 1];
        a = (int)v.x; b = (int)v.y;
    } else {
        int2 v = ((const int2*)p)[idx >> 1];
        a = v.x; b = v.y;
    }
    a = min(max(a, 0), n - 1);
    b = min(max(b, 0), n - 1);
}

// ---------------------------------------------------------------------------
// 1) count in-degree; warp-0 self-probe per block; 2 edges per thread.
__global__ void __launch_bounds__(256) k_count(const void* __restrict__ p, int E, int n) {
    __shared__ int s_dt;
    if (threadIdx.x < 32) {
        int dt = probe_dtype_warp0(p, n);
        if (threadIdx.x == 0) {
            s_dt = dt;
            if (blockIdx.x == 0) g_dtype = dt;   // publish for k_fill
        }
    }
    __syncthreads();
    int dt = s_dt;
    int e = (blockIdx.x * blockDim.x + threadIdx.x) * 2;
    if (e >= E) return;
    if (((E & 1) == 0) && (e + 1 < E)) {
        int d0, d1;
        decode2(p, (size_t)E + e, dt, n, d0, d1);
        atomicAdd(&g_cnt[d0], 1);
        atomicAdd(&g_cnt[d1], 1);
    } else {
        atomicAdd(&g_cnt[decode_id(p, (size_t)E + e, dt, n)], 1);
        if (e + 1 < E)
            atomicAdd(&g_cnt[decode_id(p, (size_t)E + e + 1, dt, n)], 1);
    }
}

// 2a) per-block exclusive scan; also computes dinv and RE-ZEROES g_cnt.
__global__ void k_scan1(int n) {
    __shared__ int s[2][SCAN_BLK];
    int t = threadIdx.x;
    int idx = blockIdx.x * SCAN_BLK + t;
    int v = (idx < n) ? g_cnt[idx] : 0;
    if (idx < n) {
        g_cnt[idx] = 0;                               // restore for next replay
        g_dinv[idx] = rsqrtf((float)v + 1.0f);
    }
    s[0][t] = v;
    __syncthreads();
    int cur = 0;
    for (int off = 1; off < SCAN_BLK; off <<= 1) {
        int nxt = cur ^ 1;
        int add = (t >= off) ? s[cur][t - off] : 0;
        s[nxt][t] = s[cur][t] + add;
        __syncthreads();
        cur = nxt;
    }
    if (idx < n) g_rowstart[idx] = s[cur][t] - v;
    if (t == SCAN_BLK - 1) g_bsum[blockIdx.x] = s[cur][t];
}

// 2b) fused: add block prefix; finalize rowstart; init cursors; rowstart[n]=E.
__global__ void __launch_bounds__(256) k_scan23(int n, int E) {
    __shared__ int s_pref;
    int seg = (blockIdx.x * 256) >> 10;
    if (threadIdx.x < 32) {
        int partial = 0;
        for (int i = threadIdx.x; i < seg; i += 32) partial += g_bsum[i];
        #pragma unroll
        for (int o = 16; o > 0; o >>= 1)
            partial += __shfl_xor_sync(0xffffffffu, partial, o);
        if (threadIdx.x == 0) s_pref = partial;
    }
    __syncthreads();
    int idx = blockIdx.x * 256 + threadIdx.x;
    if (idx == 0) g_rowstart[n] = E;
    if (idx >= n) return;
    int rs = g_rowstart[idx] + s_pref;
    g_rowstart[idx] = rs;
    g_fillpos[idx]  = rs;
}

// 3) CSR fill: src only (4 B); 2 edges per thread. No dinv load needed.
__global__ void __launch_bounds__(256) k_fill(const void* __restrict__ p, int E, int n) {
    int dt = g_dtype;
    int e = (blockIdx.x * blockDim.x + threadIdx.x) * 2;
    if (e >= E) return;
    int s0, s1, d0, d1;
    bool two = (e + 1 < E);
    if (((E & 1) == 0) && two) {
        decode2(p, (size_t)e, dt, n, s0, s1);
        decode2(p, (size_t)E + e, dt, n, d0, d1);
    } else {
        s0 = decode_id(p, (size_t)e, dt, n);
        d0 = decode_id(p, (size_t)E + e, dt, n);
        if (two) {
            s1 = decode_id(p, (size_t)e + 1, dt, n);
            d1 = decode_id(p, (size_t)E + e + 1, dt, n);
        }
    }
    int pos0 = atomicAdd(&g_fillpos[d0], 1);
    if (pos0 >= 0 && pos0 < E) g_eidx[pos0] = s0;
    if (two) {
        int pos1 = atomicAdd(&g_fillpos[d1], 1);
        if (pos1 >= 0 && pos1 < E) g_eidx[pos1] = s1;
    }
}

// ---------------------------------------------------------------------------
// GEMM1: g_h1 = dinv[row] * (x @ W1)[row]  (prescaled epilogue)
__global__ void __launch_bounds__(256) k_gemm1(const float* __restrict__ x,
                                               const float* __restrict__ W, int M) {
    __shared__ __align__(16) float Ws[CIN * CHID];
    for (int i = threadIdx.x; i < CIN * CHID; i += blockDim.x) Ws[i] = W[i];
    __syncthreads();

    int row = blockIdx.x * blockDim.x + threadIdx.x;
    if (row >= M) return;

    unsigned long long acc[CHID / 2];
    #pragma unroll
    for (int c = 0; c < CHID / 2; c++) acc[c] = 0ull;

    const float4* a4 = (const float4*)(x + (size_t)row * CIN);
    for (int k4 = 0; k4 < CIN / 4; k4++) {
        float4 xv = __ldg(a4 + k4);
        #pragma unroll
        for (int j = 0; j < 4; j++) {
            float xk = (j == 0) ? xv.x : (j == 1) ? xv.y : (j == 2) ? xv.z : xv.w;
            unsigned long long xp = pack2(xk, xk);
            const ulonglong2* w2 = (const ulonglong2*)&Ws[(4 * k4 + j) * CHID];
            #pragma unroll
            for (int c = 0; c < CHID / 4; c++) {
                ulonglong2 wv = w2[c];
                ffma2(acc[2 * c + 0], xp, wv.x);
                ffma2(acc[2 * c + 1], xp, wv.y);
            }
        }
    }
    float di = g_dinv[row];
    unsigned long long dp = pack2(di, di);
    #pragma unroll
    for (int c = 0; c < CHID / 2; c++) fmul2(acc[c], dp);
    ulonglong2* o = (ulonglong2*)&g_h1[(size_t)row * (CHID / 4)];
    #pragma unroll
    for (int c = 0; c < CHID / 4; c++)
        o[c] = make_ulonglong2(acc[2 * c], acc[2 * c + 1]);
}

// GEMM2: g_h2 = dinv[row] * (relu(g_hag) @ W2)[row]  (prescaled epilogue)
__global__ void __launch_bounds__(256) k_gemm2(const float* __restrict__ W, int M) {
    __shared__ __align__(16) float Ws[CHID * COUT];
    for (int i = threadIdx.x; i < CHID * COUT; i += blockDim.x) Ws[i] = W[i];
    __syncthreads();

    int row = blockIdx.x * blockDim.x + threadIdx.x;
    if (row >= M) return;

    unsigned long long acc[COUT / 2];
    #pragma unroll
    for (int c = 0; c < COUT / 2; c++) acc[c] = 0ull;

    const float4* a4 = (const float4*)&g_hag[(size_t)row * (CHID / 4)];
    for (int k4 = 0; k4 < CHID / 4; k4++) {
        float4 xv = a4[k4];
        xv.x = fmaxf(xv.x, 0.0f); xv.y = fmaxf(xv.y, 0.0f);
        xv.z = fmaxf(xv.z, 0.0f); xv.w = fmaxf(xv.w, 0.0f);
        #pragma unroll
        for (int j = 0; j < 4; j++) {
            float xk = (j == 0) ? xv.x : (j == 1) ? xv.y : (j == 2) ? xv.z : xv.w;
            unsigned long long xp = pack2(xk, xk);
            const ulonglong2* w2 = (const ulonglong2*)&Ws[(4 * k4 + j) * COUT];
            #pragma unroll
            for (int c = 0; c < COUT / 4; c++) {
                ulonglong2 wv = w2[c];
                ffma2(acc[2 * c + 0], xp, wv.x);
                ffma2(acc[2 * c + 1], xp, wv.y);
            }
        }
    }
    float di = g_dinv[row];
    unsigned long long dp = pack2(di, di);
    #pragma unroll
    for (int c = 0; c < COUT / 2; c++) fmul2(acc[c], dp);
    ulonglong2* o = (ulonglong2*)&g_h2[(size_t)row * (COUT / 4)];
    #pragma unroll
    for (int c = 0; c < COUT / 4; c++)
        o[c] = make_ulonglong2(acc[2 * c], acc[2 * c + 1]);
}

// ---------------------------------------------------------------------------
// Gather layer 1: hag[i] = di * (h1s[i] + Σ h1s[src]) + b1   (h1s prescaled)
__global__ void __launch_bounds__(256) k_gather1(const float* __restrict__ b1, int M) {
    int i = blockIdx.x * 8 + threadIdx.y;
    if (i >= M) return;
    int lane = threadIdx.x;
    int half = lane >> 4;                         // 0/1
    int c    = lane & 15;                         // chunk 0..15

    int start = g_rowstart[i];
    int num   = g_rowstart[i + 1] - start;

    float4 acc = make_float4(0.f, 0.f, 0.f, 0.f);
    #pragma unroll 2
    for (int j = half; j < num; j += 2) {
        int src = g_eidx[start + j];
        float4 u = g_h1[(size_t)src * (CHID/4) + c];
        acc.x += u.x; acc.y += u.y; acc.z += u.z; acc.w += u.w;
    }
    acc.x += __shfl_xor_sync(0xffffffffu, acc.x, 16);
    acc.y += __shfl_xor_sync(0xffffffffu, acc.y, 16);
    acc.z += __shfl_xor_sync(0xffffffffu, acc.z, 16);
    acc.w += __shfl_xor_sync(0xffffffffu, acc.w, 16);
    if (half == 0) {
        float di = g_dinv[i];
        float4 v = g_h1[(size_t)i * (CHID/4) + c];   // self (prescaled)
        float4 b = ((const float4*)b1)[c];
        acc.x = (acc.x + v.x) * di + b.x;
        acc.y = (acc.y + v.y) * di + b.y;
        acc.z = (acc.z + v.z) * di + b.z;
        acc.w = (acc.w + v.w) * di + b.w;
        g_hag[(size_t)i * (CHID/4) + c] = acc;
    }
}

// Gather layer 2: out[i] = di * (h2s[i] + Σ h2s[src]) + b2
__global__ void __launch_bounds__(256) k_gather2(const float* __restrict__ b2,
                                                 float* __restrict__ out, int M) {
    int i = blockIdx.x * 8 + threadIdx.y;
    if (i >= M) return;
    int lane = threadIdx.x;
    int half = lane / 10;                         // 0,1,2 (3 = idle lanes 30,31)
    int c    = lane - half * 10;                  // chunk 0..9

    int start = g_rowstart[i];
    int num   = g_rowstart[i + 1] - start;

    float4 acc = make_float4(0.f, 0.f, 0.f, 0.f);
    if (half < 3) {
        #pragma unroll 2
        for (int j = half; j < num; j += 3) {
            int src = g_eidx[start + j];
            float4 u = g_h2[(size_t)src * (COUT/4) + c];
            acc.x += u.x; acc.y += u.y; acc.z += u.z; acc.w += u.w;
        }
    }
    int l1 = (lane < 10) ? lane + 10 : lane;
    int l2 = (lane < 10) ? lane + 20 : lane;
    float ax = acc.x, ay = acc.y, az = acc.z, aw = acc.w;
    acc.x = ax + __shfl_sync(0xffffffffu, ax, l1) + __shfl_sync(0xffffffffu, ax, l2);
    acc.y = ay + __shfl_sync(0xffffffffu, ay, l1) + __shfl_sync(0xffffffffu, ay, l2);
    acc.z = az + __shfl_sync(0xffffffffu, az, l1) + __shfl_sync(0xffffffffu, az, l2);
    acc.w = aw + __shfl_sync(0xffffffffu, aw, l1) + __shfl_sync(0xffffffffu, aw, l2);
    if (lane < 10) {
        float di = g_dinv[i];
        float4 v = g_h2[(size_t)i * (COUT/4) + c];
        float4 b = ((const float4*)b2)[c];
        acc.x = (acc.x + v.x) * di + b.x;
        acc.y = (acc.y + v.y) * di + b.y;
        acc.z = (acc.z + v.z) * di + b.z;
        acc.w = (acc.w + v.w) * di + b.w;
        ((float4*)out)[(size_t)i * (COUT/4) + c] = acc;
    }
}

// ---------------------------------------------------------------------------
extern "C" void kernel_launch(void* const* d_in, const int* in_sizes, int n_in,
                              void* d_out, int out_size) {
    int M = out_size / COUT;                 // 100000

    const float* x  = nullptr;
    const float* W1 = nullptr;
    const float* b1 = nullptr;
    const float* W2 = nullptr;
    const float* b2 = nullptr;
    const void*  ei = nullptr;
    int eiElems = 0;
    for (int i = 0; i < n_in; i++) {
        int s = in_sizes[i];
        if      (s == M * CIN)      x  = (const float*)d_in[i];
        else if (s == CIN * CHID)   W1 = (const float*)d_in[i];
        else if (s == CHID)         b1 = (const float*)d_in[i];
        else if (s == CHID * COUT)  W2 = (const float*)d_in[i];
        else if (s == COUT)         b2 = (const float*)d_in[i];
        else { ei = d_in[i]; eiElems = s; }
    }
    if (!x || !W1 || !b1 || !W2 || !b2 || !ei) return;

    int E = eiElems / 2;
    if (E > EE) E = EE;
    if (M > NN) M = NN;
    int nb   = (M + SCAN_BLK - 1) / SCAN_BLK;     // 98
    int nbE2 = (E / 2 + 255) / 256;               // 3125 (2 edges/thread)
    int nbG  = (M + 255) / 256;                   // 391

    float* out = (float*)d_out;

    // Fork-join: gemm1 (needs dinv from scan1) runs parallel with fill.
    cudaStream_t s2;
    cudaEvent_t ev0, ev1;
    cudaStreamCreateWithFlags(&s2, cudaStreamNonBlocking);
    cudaEventCreateWithFlags(&ev0, cudaEventDisableTiming);
    cudaEventCreateWithFlags(&ev1, cudaEventDisableTiming);

    k_count <<<nbE2, 256>>>(ei, E, M);
    k_scan1 <<<nb, SCAN_BLK>>>(M);
    k_scan23<<<nbG, 256>>>(M, E);

    cudaEventRecord(ev0, 0);
    cudaStreamWaitEvent(s2, ev0, 0);
    k_gemm1<<<nbG, 256, 0, s2>>>(x, W1, M);       // side stream
    k_fill <<<nbE2, 256>>>(ei, E, M);             // main stream (parallel)
    cudaEventRecord(ev1, s2);
    cudaStreamWaitEvent(0, ev1, 0);

    {
        dim3 bd(32, 8);
        k_gather1<<<(M + 7) / 8, bd>>>(b1, M);
    }
    k_gemm2<<<nbG, 256>>>(W2, M);
    {
        dim3 bd(32, 8);
        k_gather2<<<(M + 7) / 8, bd>>>(b2, out, M);
    }
}

// round 14
// speedup vs baseline: 1.2016x; 1.0410x over previous
#include <cuda_runtime.h>
#include <cuda_bf16.h>
#include <stdint.h>

#define NN   100000
#define EE   1600000
#define CIN  128
#define CHID 64
#define COUT 40

// Scratch (static __device__ arrays — zero-initialized at module load)
__device__ int    g_dtype;             // 0=int32, 1=int64, 2=float32
__device__ int    g_cnt[NN];           // in-degree; RE-ZEROED by k_scan1 each run
__device__ int    g_rowstart[NN + 1];  // CSR row offsets (N+1 entries)
__device__ int    g_fillpos[NN];       // atomic cursors for CSR fill
__device__ int    g_bsum[128];         // block sums for scan
__device__ int    g_eidx[EE];          // CSR entry: src node id (4 B)
__device__ float  g_dinv[NN];
__device__ float4 g_h1 [(size_t)NN * CHID / 4];   // dinv[i] * (x@W1)[i]  (prescaled)
__device__ float4 g_hag[(size_t)NN * CHID / 4];   // layer-1 output (with b1)
__device__ float4 g_h2 [(size_t)NN * COUT / 4];   // dinv[i] * (relu(hag)@W2)[i]

#define SCAN_BLK 1024

// ---------------------------------------------------------------------------
// packed f32x2 ops
__device__ __forceinline__ void ffma2(unsigned long long& d,
                                      unsigned long long a,
                                      unsigned long long b) {
    asm volatile("fma.rn.f32x2 %0, %1, %2, %0;" : "+l"(d) : "l"(a), "l"(b));
}
__device__ __forceinline__ void fmul2(unsigned long long& d, unsigned long long a) {
    asm volatile("mul.rn.f32x2 %0, %0, %1;" : "+l"(d) : "l"(a));
}
__device__ __forceinline__ unsigned long long pack2(float lo, float hi) {
    unsigned long long r;
    asm("mov.b64 %0, {%1, %2};" : "=l"(r) : "f"(lo), "f"(hi));
    return r;
}

// In-register dtype probe over the first 32 8-byte pairs (warp 0 only).
__device__ __forceinline__ int probe_dtype_warp0(const void* p, int n) {
    const uint2* q = (const uint2*)p;
    uint2 pr = q[threadIdx.x & 31];
    unsigned odd = __ballot_sync(0xffffffffu, pr.y != 0u);
    int iv = (int)pr.x;
    unsigned iok = __ballot_sync(0xffffffffu, iv >= 0 && iv < n);
    float f = __int_as_float(iv);
    unsigned fok = __ballot_sync(0xffffffffu,
                                 f >= 0.0f && f < (float)n && f == floorf(f));
    if (odd == 0u) return 1;
    return (__popc(fok) > __popc(iok)) ? 2 : 0;
}

__device__ __forceinline__ int decode_id(const void* p, size_t idx, int dt, int n) {
    int v;
    if (dt == 1)      v = (int)((const long long*)p)[idx];
    else if (dt == 2) v = (int)((const float*)p)[idx];
    else              v = ((const int*)p)[idx];
    return min(max(v, 0), n - 1);
}

__device__ __forceinline__ void decode2(const void* p, size_t idx, int dt, int n,
                                        int& a, int& b) {
    if (dt == 1) {
        longlong2 v = ((const longlong2*)p)[idx >> 1];
        a = (int)v.x; b = (int)v.y;
    } else if (dt == 2) {
        float2 v = ((const float2*)p)[idx >> 1];
        a = (int)v.x; b = (int)v.y;
    } else {
        int2 v = ((const int2*)p)[idx >> 1];
        a = v.x; b = v.y;
    }
    a = min(max(a, 0), n - 1);
    b = min(max(b, 0), n - 1);
}

// ---------------------------------------------------------------------------
// 1) count in-degree; warp-0 self-probe per block; 2 edges per thread.
__global__ void __launch_bounds__(256) k_count(const void* __restrict__ p, int E, int n) {
    __shared__ int s_dt;
    if (threadIdx.x < 32) {
        int dt = probe_dtype_warp0(p, n);
        if (threadIdx.x == 0) {
            s_dt = dt;
            if (blockIdx.x == 0) g_dtype = dt;   // publish for k_fill
        }
    }
    __syncthreads();
    int dt = s_dt;
    int e = (blockIdx.x * blockDim.x + threadIdx.x) * 2;
    if (e >= E) return;
    if (((E & 1) == 0) && (e + 1 < E)) {
        int d0, d1;
        decode2(p, (size_t)E + e, dt, n, d0, d1);
        atomicAdd(&g_cnt[d0], 1);
        atomicAdd(&g_cnt[d1], 1);
    } else {
        atomicAdd(&g_cnt[decode_id(p, (size_t)E + e, dt, n)], 1);
        if (e + 1 < E)
            atomicAdd(&g_cnt[decode_id(p, (size_t)E + e + 1, dt, n)], 1);
    }
}

// 2a) per-block exclusive scan; also computes dinv and RE-ZEROES g_cnt.
__global__ void k_scan1(int n) {
    __shared__ int s[2][SCAN_BLK];
    int t = threadIdx.x;
    int idx = blockIdx.x * SCAN_BLK + t;
    int v = (idx < n) ? g_cnt[idx] : 0;
    if (idx < n) {
        g_cnt[idx] = 0;
        g_dinv[idx] = rsqrtf((float)v + 1.0f);
    }
    s[0][t] = v;
    __syncthreads();
    int cur = 0;
    for (int off = 1; off < SCAN_BLK; off <<= 1) {
        int nxt = cur ^ 1;
        int add = (t >= off) ? s[cur][t - off] : 0;
        s[nxt][t] = s[cur][t] + add;
        __syncthreads();
        cur = nxt;
    }
    if (idx < n) g_rowstart[idx] = s[cur][t] - v;
    if (t == SCAN_BLK - 1) g_bsum[blockIdx.x] = s[cur][t];
}

// 2b) fused: add block prefix; finalize rowstart; init cursors; rowstart[n]=E.
__global__ void __launch_bounds__(256) k_scan23(int n, int E) {
    __shared__ int s_pref;
    int seg = (blockIdx.x * 256) >> 10;
    if (threadIdx.x < 32) {
        int partial = 0;
        for (int i = threadIdx.x; i < seg; i += 32) partial += g_bsum[i];
        #pragma unroll
        for (int o = 16; o > 0; o >>= 1)
            partial += __shfl_xor_sync(0xffffffffu, partial, o);
        if (threadIdx.x == 0) s_pref = partial;
    }
    __syncthreads();
    int idx = blockIdx.x * 256 + threadIdx.x;
    if (idx == 0) g_rowstart[n] = E;
    if (idx >= n) return;
    int rs = g_rowstart[idx] + s_pref;
    g_rowstart[idx] = rs;
    g_fillpos[idx]  = rs;
}

// 3) CSR fill: src only (4 B); 2 edges per thread.
__global__ void __launch_bounds__(256) k_fill(const void* __restrict__ p, int E, int n) {
    int dt = g_dtype;
    int e = (blockIdx.x * blockDim.x + threadIdx.x) * 2;
    if (e >= E) return;
    int s0, s1, d0, d1;
    bool two = (e + 1 < E);
    if (((E & 1) == 0) && two) {
        decode2(p, (size_t)e, dt, n, s0, s1);
        decode2(p, (size_t)E + e, dt, n, d0, d1);
    } else {
        s0 = decode_id(p, (size_t)e, dt, n);
        d0 = decode_id(p, (size_t)E + e, dt, n);
        if (two) {
            s1 = decode_id(p, (size_t)e + 1, dt, n);
            d1 = decode_id(p, (size_t)E + e + 1, dt, n);
        }
    }
    int pos0 = atomicAdd(&g_fillpos[d0], 1);
    if (pos0 >= 0 && pos0 < E) g_eidx[pos0] = s0;
    if (two) {
        int pos1 = atomicAdd(&g_fillpos[d1], 1);
        if (pos1 >= 0 && pos1 < E) g_eidx[pos1] = s1;
    }
}

// ---------------------------------------------------------------------------
// Tiled GEMM1: g_h1 = dinv * (x @ W1). 64x64 tile, K in 2 slabs of 64,
// 4x4 micro-tile per thread, FFMA2 accumulators.
__global__ void __launch_bounds__(256) k_gemm1t(const float* __restrict__ x,
                                                const float* __restrict__ W, int M) {
    __shared__ __align__(16) float Xs[64][65];   // padded: conflict-free a-loads
    __shared__ __align__(16) float Ws[64][CHID]; // one K-slab of W1
    int t  = threadIdx.x;
    int tr = t & 15;          // row micro-tile 0..15
    int tc = t >> 4;          // col micro-tile 0..15
    int row0 = blockIdx.x * 64;

    unsigned long long acc[4][2];
    #pragma unroll
    for (int i = 0; i < 4; i++) { acc[i][0] = 0ull; acc[i][1] = 0ull; }

    for (int ks = 0; ks < CIN; ks += 64) {
        #pragma unroll
        for (int l = 0; l < 4; l++) {
            int idx = t + l * 256;                 // 0..1023
            int r = idx >> 4, k4 = idx & 15;
            float4 v = make_float4(0.f, 0.f, 0.f, 0.f);
            if (row0 + r < M)
                v = __ldg((const float4*)(x + (size_t)(row0 + r) * CIN + ks) + k4);
            Xs[r][4*k4+0] = v.x; Xs[r][4*k4+1] = v.y;
            Xs[r][4*k4+2] = v.z; Xs[r][4*k4+3] = v.w;
        }
        #pragma unroll
        for (int l = 0; l < 4; l++) {
            int idx = t + l * 256;                 // 0..1023 float4s
            ((float4*)Ws)[idx] = __ldg((const float4*)(W + ks * CHID) + idx);
        }
        __syncthreads();

        #pragma unroll 4
        for (int k = 0; k < 64; k++) {
            ulonglong2 bv = *(const ulonglong2*)&Ws[k][tc * 4];
            #pragma unroll
            for (int i = 0; i < 4; i++) {
                float a = Xs[tr * 4 + i][k];
                unsigned long long ap = pack2(a, a);
                ffma2(acc[i][0], ap, bv.x);
                ffma2(acc[i][1], ap, bv.y);
            }
        }
        __syncthreads();
    }

    #pragma unroll
    for (int i = 0; i < 4; i++) {
        int row = row0 + tr * 4 + i;
        if (row < M) {
            float d = g_dinv[row];
            unsigned long long dp = pack2(d, d);
            fmul2(acc[i][0], dp);
            fmul2(acc[i][1], dp);
            *((ulonglong2*)&g_h1[(size_t)row * (CHID / 4) + tc]) =
                make_ulonglong2(acc[i][0], acc[i][1]);
        }
    }
}

// Tiled GEMM2: g_h2 = dinv * (relu(g_hag) @ W2). 64-row tile, K=64 single slab,
// 16x10 thread grid (160 threads), 4x4 micro-tile.
__global__ void __launch_bounds__(160) k_gemm2t(const float* __restrict__ W, int M) {
    __shared__ __align__(16) float Hs[64][65];
    __shared__ __align__(16) float Ws[CHID][COUT];   // 64x40
    int t  = threadIdx.x;
    int tr = t % 16;          // 0..15
    int tc = t / 16;          // 0..9
    int row0 = blockIdx.x * 64;

    for (int idx = t; idx < 64 * 16; idx += 160) {
        int r = idx >> 4, k4 = idx & 15;
        float4 v = make_float4(0.f, 0.f, 0.f, 0.f);
        if (row0 + r < M) v = g_hag[(size_t)(row0 + r) * (CHID / 4) + k4];
        Hs[r][4*k4+0] = fmaxf(v.x, 0.f); Hs[r][4*k4+1] = fmaxf(v.y, 0.f);
        Hs[r][4*k4+2] = fmaxf(v.z, 0.f); Hs[r][4*k4+3] = fmaxf(v.w, 0.f);
    }
    for (int idx = t; idx < CHID * COUT / 4; idx += 160)
        ((float4*)Ws)[idx] = __ldg((const float4*)W + idx);
    __syncthreads();

    unsigned long long acc[4][2];
    #pragma unroll
    for (int i = 0; i < 4; i++) { acc[i][0] = 0ull; acc[i][1] = 0ull; }

    #pragma unroll 4
    for (int k = 0; k < CHID; k++) {
        ulonglong2 bv = *(const ulonglong2*)&Ws[k][tc * 4];
        #pragma unroll
        for (int i = 0; i < 4; i++) {
            float a = Hs[tr * 4 + i][k];
            unsigned long long ap = pack2(a, a);
            ffma2(acc[i][0], ap, bv.x);
            ffma2(acc[i][1], ap, bv.y);
        }
    }

    #pragma unroll
    for (int i = 0; i < 4; i++) {
        int row = row0 + tr * 4 + i;
        if (row < M) {
            float d = g_dinv[row];
            unsigned long long dp = pack2(d, d);
            fmul2(acc[i][0], dp);
            fmul2(acc[i][1], dp);
            *((ulonglong2*)&g_h2[(size_t)row * (COUT / 4) + tc]) =
                make_ulonglong2(acc[i][0], acc[i][1]);
        }
    }
}

// ---------------------------------------------------------------------------
// Gather layer 1: hag[i] = di * (h1s[i] + Σ h1s[src]) + b1   (h1s prescaled)
__global__ void __launch_bounds__(256) k_gather1(const float* __restrict__ b1, int M) {
    int i = blockIdx.x * 8 + threadIdx.y;
    if (i >= M) return;
    int lane = threadIdx.x;
    int half = lane >> 4;
    int c    = lane & 15;

    int start = g_rowstart[i];
    int num   = g_rowstart[i + 1] - start;

    float4 acc = make_float4(0.f, 0.f, 0.f, 0.f);
    #pragma unroll 2
    for (int j = half; j < num; j += 2) {
        int src = g_eidx[start + j];
        float4 u = g_h1[(size_t)src * (CHID/4) + c];
        acc.x += u.x; acc.y += u.y; acc.z += u.z; acc.w += u.w;
    }
    acc.x += __shfl_xor_sync(0xffffffffu, acc.x, 16);
    acc.y += __shfl_xor_sync(0xffffffffu, acc.y, 16);
    acc.z += __shfl_xor_sync(0xffffffffu, acc.z, 16);
    acc.w += __shfl_xor_sync(0xffffffffu, acc.w, 16);
    if (half == 0) {
        float di = g_dinv[i];
        float4 v = g_h1[(size_t)i * (CHID/4) + c];
        float4 b = ((const float4*)b1)[c];
        acc.x = (acc.x + v.x) * di + b.x;
        acc.y = (acc.y + v.y) * di + b.y;
        acc.z = (acc.z + v.z) * di + b.z;
        acc.w = (acc.w + v.w) * di + b.w;
        g_hag[(size_t)i * (CHID/4) + c] = acc;
    }
}

// Gather layer 2: out[i] = di * (h2s[i] + Σ h2s[src]) + b2
__global__ void __launch_bounds__(256) k_gather2(const float* __restrict__ b2,
                                                 float* __restrict__ out, int M) {
    int i = blockIdx.x * 8 + threadIdx.y;
    if (i >= M) return;
    int lane = threadIdx.x;
    int half = lane / 10;
    int c    = lane - half * 10;

    int start = g_rowstart[i];
    int num   = g_rowstart[i + 1] - start;

    float4 acc = make_float4(0.f, 0.f, 0.f, 0.f);
    if (half < 3) {
        #pragma unroll 2
        for (int j = half; j < num; j += 3) {
            int src = g_eidx[start + j];
            float4 u = g_h2[(size_t)src * (COUT/4) + c];
            acc.x += u.x; acc.y += u.y; acc.z += u.z; acc.w += u.w;
        }
    }
    int l1 = (lane < 10) ? lane + 10 : lane;
    int l2 = (lane < 10) ? lane + 20 : lane;
    float ax = acc.x, ay = acc.y, az = acc.z, aw = acc.w;
    acc.x = ax + __shfl_sync(0xffffffffu, ax, l1) + __shfl_sync(0xffffffffu, ax, l2);
    acc.y = ay + __shfl_sync(0xffffffffu, ay, l1) + __shfl_sync(0xffffffffu, ay, l2);
    acc.z = az + __shfl_sync(0xffffffffu, az, l1) + __shfl_sync(0xffffffffu, az, l2);
    acc.w = aw + __shfl_sync(0xffffffffu, aw, l1) + __shfl_sync(0xffffffffu, aw, l2);
    if (lane < 10) {
        float di = g_dinv[i];
        float4 v = g_h2[(size_t)i * (COUT/4) + c];
        float4 b = ((const float4*)b2)[c];
        acc.x = (acc.x + v.x) * di + b.x;
        acc.y = (acc.y + v.y) * di + b.y;
        acc.z = (acc.z + v.z) * di + b.z;
        acc.w = (acc.w + v.w) * di + b.w;
        ((float4*)out)[(size_t)i * (COUT/4) + c] = acc;
    }
}

// ---------------------------------------------------------------------------
extern "C" void kernel_launch(void* const* d_in, const int* in_sizes, int n_in,
                              void* d_out, int out_size) {
    int M = out_size / COUT;                 // 100000

    const float* x  = nullptr;
    const float* W1 = nullptr;
    const float* b1 = nullptr;
    const float* W2 = nullptr;
    const float* b2 = nullptr;
    const void*  ei = nullptr;
    int eiElems = 0;
    for (int i = 0; i < n_in; i++) {
        int s = in_sizes[i];
        if      (s == M * CIN)      x  = (const float*)d_in[i];
        else if (s == CIN * CHID)   W1 = (const float*)d_in[i];
        else if (s == CHID)         b1 = (const float*)d_in[i];
        else if (s == CHID * COUT)  W2 = (const float*)d_in[i];
        else if (s == COUT)         b2 = (const float*)d_in[i];
        else { ei = d_in[i]; eiElems = s; }
    }
    if (!x || !W1 || !b1 || !W2 || !b2 || !ei) return;

    int E = eiElems / 2;
    if (E > EE) E = EE;
    if (M > NN) M = NN;
    int nb   = (M + SCAN_BLK - 1) / SCAN_BLK;     // 98
    int nbE2 = (E / 2 + 255) / 256;               // 3125
    int nbG  = (M + 255) / 256;                   // 391
    int nbT  = (M + 63) / 64;                     // 1563 (tiled gemms)

    float* out = (float*)d_out;

    // Fork-join: gemm1 needs only dinv (scan1) — overlap with scan23 + fill.
    cudaStream_t s2;
    cudaEvent_t ev0, ev1;
    cudaStreamCreateWithFlags(&s2, cudaStreamNonBlocking);
    cudaEventCreateWithFlags(&ev0, cudaEventDisableTiming);
    cudaEventCreateWithFlags(&ev1, cudaEventDisableTiming);

    k_count <<<nbE2, 256>>>(ei, E, M);
    k_scan1 <<<nb, SCAN_BLK>>>(M);

    cudaEventRecord(ev0, 0);
    cudaStreamWaitEvent(s2, ev0, 0);
    k_gemm1t<<<nbT, 256, 0, s2>>>(x, W1, M);      // side stream
    k_scan23<<<nbG, 256>>>(M, E);                 // main stream (parallel)
    k_fill  <<<nbE2, 256>>>(ei, E, M);
    cudaEventRecord(ev1, s2);
    cudaStreamWaitEvent(0, ev1, 0);

    {
        dim3 bd(32, 8);
        k_gather1<<<(M + 7) / 8, bd>>>(b1, M);
    }
    k_gemm2t<<<nbT, 160>>>(W2, M);
    {
        dim3 bd(32, 8);
        k_gather2<<<(M + 7) / 8, bd>>>(b2, out, M);
    }
}